// round 9
// baseline (speedup 1.0000x reference)
#include <cuda_runtime.h>
#include <cstdint>

// out[b,p,d] = (sum_h hs[b,p,h] * W[prop[b,p], h, d] + bias[prop[b,p], d]) * mask[b,p]
// B=512, P=128 -> 65536 rows, H=512, D=2. One warp per row.
// Hybrid staging: hs (DRAM stream) front-batched into 4 float4 REGISTERS (__ldcs,
// evict-first keeps W L2-resident); W (L2 gather) staged via 8x cp.async into
// 4KB smem/warp (zero register residency in flight). Warp blocks once.
// W smem layout de-interleaved: smem idx (g&1)*128 + (g>>1) for W float4 g,
// so consume is two linear conflict-free LDS.128 streams matching lane-held h.

#define NROWS 65536
#define HDIM 512
#define WPB 8

__global__ __launch_bounds__(32 * WPB) void adapter_kernel(
    const float* __restrict__ hs,          // [65536, 512]
    const int* __restrict__ props,         // [65536] int32
    const float* __restrict__ mask,        // [65536]
    const float* __restrict__ W,           // [10000, 512, 2]
    const float* __restrict__ bias,        // [10000, 2]
    float* __restrict__ out)               // [65536, 2]
{
    __shared__ float4 wbuf[WPB][256];      // 4KB per warp

    const int warp = threadIdx.x >> 5;
    const int lane = threadIdx.x & 31;
    const int row = blockIdx.x * WPB + warp;

    const int p = __ldg(&props[row]);

    const float4* __restrict__ h4 = reinterpret_cast<const float4*>(hs + (size_t)row * HDIM);
    const float4* __restrict__ w4 = reinterpret_cast<const float4*>(W + (size_t)p * (HDIM * 2));

    // ---- front-batch hs (DRAM latency) into registers, streaming hint ----
    float4 h0 = __ldcs(&h4[lane]);
    float4 h1 = __ldcs(&h4[32 + lane]);
    float4 h2 = __ldcs(&h4[64 + lane]);
    float4 h3 = __ldcs(&h4[96 + lane]);

    // ---- W via cp.async into de-interleaved smem (L2 hits, no reg residency) ----
    // g = i*32 + lane; dst index = (g&1)*128 + (g>>1)
    #pragma unroll
    for (int i = 0; i < 8; i++) {
        const int g = i * 32 + lane;
        const int di = (g & 1) * 128 + (g >> 1);
        uint32_t dst = (uint32_t)__cvta_generic_to_shared(&wbuf[warp][di]);
        asm volatile("cp.async.cg.shared.global [%0], [%1], 16;"
                     :: "r"(dst), "l"(w4 + g) : "memory");
    }
    asm volatile("cp.async.commit_group;" ::: "memory");
    asm volatile("cp.async.wait_group 0;" ::: "memory");
    __syncwarp();   // consume reads cross-lane W copies

    // ---- consume: wa = w4[2k] at smem[k], wb = w4[2k+1] at smem[128+k] ----
    float acc0 = 0.f, acc1 = 0.f;
    #pragma unroll
    for (int i = 0; i < 4; i++) {
        const int k = i * 32 + lane;
        const float4 wa = wbuf[warp][k];          // h=4k:(w00,w01), h=4k+1:(w10,w11)
        const float4 wb = wbuf[warp][128 + k];    // h=4k+2, h=4k+3
        const float4 hh = (i == 0) ? h0 : (i == 1) ? h1 : (i == 2) ? h2 : h3;
        acc0 = fmaf(hh.x, wa.x, acc0);
        acc1 = fmaf(hh.x, wa.y, acc1);
        acc0 = fmaf(hh.y, wa.z, acc0);
        acc1 = fmaf(hh.y, wa.w, acc1);
        acc0 = fmaf(hh.z, wb.x, acc0);
        acc1 = fmaf(hh.z, wb.y, acc1);
        acc0 = fmaf(hh.w, wb.z, acc0);
        acc1 = fmaf(hh.w, wb.w, acc1);
    }

    // Warp tree reduction
    #pragma unroll
    for (int off = 16; off > 0; off >>= 1) {
        acc0 += __shfl_xor_sync(0xFFFFFFFFu, acc0, off);
        acc1 += __shfl_xor_sync(0xFFFFFFFFu, acc1, off);
    }

    if (lane == 0) {
        const float m = mask[row];
        const float b0 = __ldg(&bias[p * 2 + 0]);
        const float b1 = __ldg(&bias[p * 2 + 1]);
        float2 r;
        r.x = (acc0 + b0) * m;
        r.y = (acc1 + b1) * m;
        __stcs(reinterpret_cast<float2*>(out) + row, r);
    }
}

extern "C" void kernel_launch(void* const* d_in, const int* in_sizes, int n_in,
                              void* d_out, int out_size)
{
    const float* hs    = (const float*)d_in[0];
    const int*   props = (const int*)d_in[1];
    const float* mask  = (const float*)d_in[2];
    const float* W     = (const float*)d_in[3];
    const float* bias  = (const float*)d_in[4];
    float*       out   = (float*)d_out;

    const int threads = 32 * WPB;
    const int blocks = NROWS / WPB;
    adapter_kernel<<<blocks, threads>>>(hs, props, mask, W, bias, out);
}

// round 10
// speedup vs baseline: 2.0162x; 2.0162x over previous
#include <cuda_runtime.h>
#include <cstdint>

// out[b,p,d] = (sum_h hs[b,p,h] * W[prop[b,p], h, d] + bias[prop[b,p], d]) * mask[b,p]
// B=512, P=128 -> 65536 rows, H=512, D=2. One warp per row.
// Hybrid staging: hs (DRAM stream) front-batched into 4 float4 REGISTERS (__ldcs,
// evict-first keeps W L2-resident); W (L2 gather) staged via 8x cp.async into
// 4KB smem/warp with LINEAR destinations (lanes contiguous -> single wavefront
// per cp.async). Layout handled at consume: wa=wbuf[2k], wb=wbuf[2k+1]
// (stride-32B LDS.128, 2-phase, negligible). Warp blocks once on wait_group.

#define NROWS 65536
#define HDIM 512
#define WPB 8

__global__ __launch_bounds__(32 * WPB) void adapter_kernel(
    const float* __restrict__ hs,          // [65536, 512]
    const int* __restrict__ props,         // [65536] int32
    const float* __restrict__ mask,        // [65536]
    const float* __restrict__ W,           // [10000, 512, 2]
    const float* __restrict__ bias,        // [10000, 2]
    float* __restrict__ out)               // [65536, 2]
{
    __shared__ float4 wbuf[WPB][256];      // 4KB per warp

    const int warp = threadIdx.x >> 5;
    const int lane = threadIdx.x & 31;
    const int row = blockIdx.x * WPB + warp;

    const int p = __ldg(&props[row]);

    const float4* __restrict__ h4 = reinterpret_cast<const float4*>(hs + (size_t)row * HDIM);
    const float4* __restrict__ w4 = reinterpret_cast<const float4*>(W + (size_t)p * (HDIM * 2));

    // ---- front-batch hs (DRAM latency) into registers, streaming hint ----
    float4 h0 = __ldcs(&h4[lane]);
    float4 h1 = __ldcs(&h4[32 + lane]);
    float4 h2 = __ldcs(&h4[64 + lane]);
    float4 h3 = __ldcs(&h4[96 + lane]);

    // ---- W via cp.async, LINEAR smem destinations (contiguous per warp) ----
    #pragma unroll
    for (int i = 0; i < 8; i++) {
        const int g = i * 32 + lane;
        uint32_t dst = (uint32_t)__cvta_generic_to_shared(&wbuf[warp][g]);
        asm volatile("cp.async.cg.shared.global [%0], [%1], 16;"
                     :: "r"(dst), "l"(w4 + g) : "memory");
    }
    asm volatile("cp.async.commit_group;" ::: "memory");
    asm volatile("cp.async.wait_group 0;" ::: "memory");
    __syncwarp();   // consume reads cross-lane W copies

    // ---- consume: for lane-held h4[k], W pairs live at wbuf[2k], wbuf[2k+1] ----
    float acc0 = 0.f, acc1 = 0.f;
    #pragma unroll
    for (int i = 0; i < 4; i++) {
        const int k = i * 32 + lane;
        const float4 wa = wbuf[warp][2 * k];       // h=4k:(w00,w01), h=4k+1:(w10,w11)
        const float4 wb = wbuf[warp][2 * k + 1];   // h=4k+2, h=4k+3
        const float4 hh = (i == 0) ? h0 : (i == 1) ? h1 : (i == 2) ? h2 : h3;
        acc0 = fmaf(hh.x, wa.x, acc0);
        acc1 = fmaf(hh.x, wa.y, acc1);
        acc0 = fmaf(hh.y, wa.z, acc0);
        acc1 = fmaf(hh.y, wa.w, acc1);
        acc0 = fmaf(hh.z, wb.x, acc0);
        acc1 = fmaf(hh.z, wb.y, acc1);
        acc0 = fmaf(hh.w, wb.z, acc0);
        acc1 = fmaf(hh.w, wb.w, acc1);
    }

    // Warp tree reduction
    #pragma unroll
    for (int off = 16; off > 0; off >>= 1) {
        acc0 += __shfl_xor_sync(0xFFFFFFFFu, acc0, off);
        acc1 += __shfl_xor_sync(0xFFFFFFFFu, acc1, off);
    }

    if (lane == 0) {
        const float m = mask[row];
        const float b0 = __ldg(&bias[p * 2 + 0]);
        const float b1 = __ldg(&bias[p * 2 + 1]);
        float2 r;
        r.x = (acc0 + b0) * m;
        r.y = (acc1 + b1) * m;
        __stcs(reinterpret_cast<float2*>(out) + row, r);
    }
}

extern "C" void kernel_launch(void* const* d_in, const int* in_sizes, int n_in,
                              void* d_out, int out_size)
{
    const float* hs    = (const float*)d_in[0];
    const int*   props = (const int*)d_in[1];
    const float* mask  = (const float*)d_in[2];
    const float* W     = (const float*)d_in[3];
    const float* bias  = (const float*)d_in[4];
    float*       out   = (float*)d_out;

    const int threads = 32 * WPB;
    const int blocks = NROWS / WPB;
    adapter_kernel<<<blocks, threads>>>(hs, props, mask, W, bias, out);
}